// round 15
// baseline (speedup 1.0000x reference)
#include <cuda_runtime.h>
#include <cuda_fp16.h>
#include <cstdint>

// MoE dense 8-expert: D_IN=6, H=32, D_OUT=2, B=1M, fp32.
// R15 = R14 math (all four GEMMs on fp16 mma.sync, minimal MMA count) with
// TWO 32-token half-tiles per warp processed back-to-back inside the expert
// loop: per-expert fragments loaded once, and tile-B's independent MMA chain
// fills tile-A's cvt/HMMA-latency stalls (intra-warp ILP instead of
// occupancy). launch_bounds(128,2) for scheduling freedom, grid = 2 CTAs/SM.

#define ED 8
#define DI 6
#define HH 32
#define DO 2

typedef unsigned long long u64;
typedef unsigned int u32;

__device__ __forceinline__ u32 f16x2_of(float lo_e, float hi_e) {
    u32 r; asm("cvt.rn.f16x2.f32 %0, %1, %2;" : "=r"(r) : "f"(hi_e), "f"(lo_e)); return r;
}
__device__ __forceinline__ u32 hmax2z(u32 a) {
    u32 r; asm("max.f16x2 %0, %1, %2;" : "=r"(r) : "r"(a), "r"(0u)); return r;
}
__device__ __forceinline__ u32 hmul2(u32 a, u32 b) {
    u32 r; asm("mul.f16x2 %0, %1, %2;" : "=r"(r) : "r"(a), "r"(b)); return r;
}
__device__ __forceinline__ void ffma2_acc(u64& acc, u64 a, u64 b) {
    asm("fma.rn.f32x2 %0, %1, %2, %0;" : "+l"(acc) : "l"(a), "l"(b));
}
__device__ __forceinline__ u64 mul2(u64 a, u64 b) {
    u64 r; asm("mul.rn.f32x2 %0, %1, %2;" : "=l"(r) : "l"(a), "l"(b)); return r;
}
__device__ __forceinline__ u64 add2(u64 a, u64 b) {
    u64 r; asm("add.rn.f32x2 %0, %1, %2;" : "=l"(r) : "l"(a), "l"(b)); return r;
}
__device__ __forceinline__ u64 pack_dup(float v) {
    u64 r; asm("mov.b64 %0, {%1, %1};" : "=l"(r) : "r"(__float_as_uint(v))); return r;
}
__device__ __forceinline__ float2 unpack2(u64 v) {
    float2 f; asm("mov.b64 {%0, %1}, %2;" : "=f"(f.x), "=f"(f.y) : "l"(v)); return f;
}

// ---- MMA helpers (fp16 in, fp32 accum) ----
__device__ __forceinline__ void mma_f16(float& d0, float& d1, float& d2, float& d3,
                                        u32 a0, u32 a1, u32 a2, u32 a3,
                                        u32 b0, u32 b1) {
    asm("mma.sync.aligned.m16n8k16.row.col.f32.f16.f16.f32 "
        "{%0,%1,%2,%3}, {%4,%5,%6,%7}, {%8,%9}, {%0,%1,%2,%3};"
        : "+f"(d0), "+f"(d1), "+f"(d2), "+f"(d3)
        : "r"(a0), "r"(a1), "r"(a2), "r"(a3), "r"(b0), "r"(b1));
}
__device__ __forceinline__ void mma_f16_c(float& d0, float& d1, float& d2, float& d3,
                                          u32 a0, u32 a1, u32 a2, u32 a3,
                                          u32 b0, u32 b1,
                                          float c0, float c1, float c2, float c3) {
    asm("mma.sync.aligned.m16n8k16.row.col.f32.f16.f16.f32 "
        "{%0,%1,%2,%3}, {%4,%5,%6,%7}, {%8,%9}, {%10,%11,%12,%13};"
        : "=f"(d0), "=f"(d1), "=f"(d2), "=f"(d3)
        : "r"(a0), "r"(a1), "r"(a2), "r"(a3), "r"(b0), "r"(b1),
          "f"(c0), "f"(c1), "f"(c2), "f"(c3));
}
__device__ __forceinline__ void mma_f16_k8_c(float& d0, float& d1, float& d2, float& d3,
                                             u32 a0, u32 a1, u32 b0,
                                             float c0, float c1, float c2, float c3) {
    asm("mma.sync.aligned.m16n8k8.row.col.f32.f16.f16.f32 "
        "{%0,%1,%2,%3}, {%4,%5}, {%6}, {%7,%8,%9,%10};"
        : "=f"(d0), "=f"(d1), "=f"(d2), "=f"(d3)
        : "r"(a0), "r"(a1), "r"(b0),
          "f"(c0), "f"(c1), "f"(c2), "f"(c3));
}

__global__ __launch_bounds__(128, 2)
void moe_mma_kernel(const float* __restrict__ gx,
                    const float* __restrict__ gW1, const float* __restrict__ gb1,
                    const float* __restrict__ gW2, const float* __restrict__ gb2,
                    const float* __restrict__ gW3, const float* __restrict__ gb3,
                    const float* __restrict__ gWg1, const float* __restrict__ gbg1,
                    const float* __restrict__ gWg2, const float* __restrict__ gbg2,
                    float* __restrict__ gout, int B, int NT)
{
    __shared__ __align__(16) float sx[4 * 384];               // per-warp x (64 tok x 6)
    __shared__ __align__(16) char  sBfrag[ED * 4 * 32 * 16];  // layer-2 W2 fp16 frags
    __shared__ __align__(16) char  sB1frag[ED * 32 * 16];     // layer-1 W1 fp16 frags, b1 @k=6
    __shared__ __align__(16) char  sG1frag[32 * 16];          // gate Wg1 frag, bg1 @k=6
    __shared__ __align__(16) char  sG2frag[32 * 16];          // gate Wg2 frag (K=32, N=8)
    __shared__ __align__(16) float sb2[ED * HH];

    const int tid  = threadIdx.x;
    const int w    = tid >> 5;
    const int lane = tid & 31;
    const int g    = lane >> 2;   // groupID
    const int q    = lane & 3;    // threadID in group

    for (int i = tid; i < ED * HH; i += 128) sb2[i] = gb2[i];

    // ---- precompute per-lane B fragments (fp16) ----
    for (int e = w * 2; e < w * 2 + 2; e++) {
        #pragma unroll
        for (int c = 0; c < 4; c++) {
            const int kf = c >> 1, nfh = c & 1;
            u32 hi4[4];
            #pragma unroll
            for (int p = 0; p < 2; p++) {
                const int n  = (nfh * 2 + p) * 8 + g;
                const int k0 = kf * 16 + 2 * q;
                hi4[p * 2 + 0] = f16x2_of(gW2[e * 1024 + (k0    ) * 32 + n],
                                          gW2[e * 1024 + (k0 + 1) * 32 + n]);
                hi4[p * 2 + 1] = f16x2_of(gW2[e * 1024 + (k0 + 8) * 32 + n],
                                          gW2[e * 1024 + (k0 + 9) * 32 + n]);
            }
            *(uint4*)(sBfrag + ((e * 4 + c) * 32 + lane) * 16) = make_uint4(hi4[0], hi4[1], hi4[2], hi4[3]);
        }
        {
            u32 hi4[4];
            #pragma unroll
            for (int nf = 0; nf < 4; nf++) {
                const int n = nf * 8 + g;
                float w0, w1;
                if (q < 3) {
                    w0 = gW1[e * 192 + (2 * q    ) * 32 + n];
                    w1 = gW1[e * 192 + (2 * q + 1) * 32 + n];
                } else {
                    w0 = gb1[e * 32 + n];
                    w1 = 0.0f;
                }
                hi4[nf] = f16x2_of(w0, w1);
            }
            *(uint4*)(sB1frag + (e * 32 + lane) * 16) = make_uint4(hi4[0], hi4[1], hi4[2], hi4[3]);
        }
    }
    if (w == 0) {
        u32 hi4[4];
        #pragma unroll
        for (int nf = 0; nf < 4; nf++) {
            const int n = nf * 8 + g;
            float w0, w1;
            if (q < 3) {
                w0 = gWg1[(2 * q    ) * 32 + n];
                w1 = gWg1[(2 * q + 1) * 32 + n];
            } else {
                w0 = gbg1[n];
                w1 = 0.0f;
            }
            hi4[nf] = f16x2_of(w0, w1);
        }
        *(uint4*)(sG1frag + lane * 16) = make_uint4(hi4[0], hi4[1], hi4[2], hi4[3]);
    }
    if (w == 1) {
        u32 f4[4];
        #pragma unroll
        for (int kf = 0; kf < 2; kf++) {
            const int k0 = kf * 16 + 2 * q;
            f4[kf * 2 + 0] = f16x2_of(gWg2[(k0    ) * ED + g], gWg2[(k0 + 1) * ED + g]);
            f4[kf * 2 + 1] = f16x2_of(gWg2[(k0 + 8) * ED + g], gWg2[(k0 + 9) * ED + g]);
        }
        *(uint4*)(sG2frag + lane * 16) = make_uint4(f4[0], f4[1], f4[2], f4[3]);
    }
    __syncthreads();

    // ---- layer-3 W3 B-fragments in registers (K=32, N=8; cols>=2 zero) ----
    u32 w3f[ED][4];
    #pragma unroll
    for (int e = 0; e < ED; e++) {
        #pragma unroll
        for (int kf = 0; kf < 2; kf++) {
            const int k0 = kf * 16 + 2 * q;
            u32 b0 = 0, b1 = 0;
            if (g < 2) {
                b0 = f16x2_of(gW3[e * 64 + (k0    ) * DO + g], gW3[e * 64 + (k0 + 1) * DO + g]);
                b1 = f16x2_of(gW3[e * 64 + (k0 + 8) * DO + g], gW3[e * 64 + (k0 + 9) * DO + g]);
            }
            w3f[e][kf * 2 + 0] = b0;
            w3f[e][kf * 2 + 1] = b1;
        }
    }
    const u64 b3q0 = *(const u64*)&gb3[(2 * q    ) * DO];
    const u64 b3q1 = *(const u64*)&gb3[(2 * q + 1) * DO];

    const int lim6 = B * DI;
    const float fz = 0.0f;
    const float2 bg2c = ((const float2*)gbg2)[q];

    // ---- persistent loop: 64 tokens per warp (two 32-token half-tiles) ----
    for (int tile = blockIdx.x; tile < NT; tile += gridDim.x) {
        const int base = tile * 256 + w * 64;
        float* sxw = sx + w * 384;
        #pragma unroll
        for (int i = 0; i < 12; i++) {
            const int idx = base * DI + i * 32 + lane;
            sxw[i * 32 + lane] = (idx < lim6) ? gx[idx] : 0.0f;
        }
        __syncwarp();

        // ---- x A-fragments for both half-tiles ----
        u32 xhi[2][2][2];   // [t][mf][reg]
        #pragma unroll
        for (int t = 0; t < 2; t++) {
            #pragma unroll
            for (int mf = 0; mf < 2; mf++) {
                const int r0 = t * 32 + 16 * mf + g, r1 = r0 + 8;
                float v00, v01, v10, v11;
                if (q < 3) {
                    v00 = sxw[r0 * DI + 2 * q]; v01 = sxw[r0 * DI + 2 * q + 1];
                    v10 = sxw[r1 * DI + 2 * q]; v11 = sxw[r1 * DI + 2 * q + 1];
                } else {
                    v00 = 1.0f; v01 = 0.0f; v10 = 1.0f; v11 = 0.0f;
                }
                xhi[t][mf][0] = f16x2_of(v00, v01);
                xhi[t][mf][1] = f16x2_of(v10, v11);
            }
        }

        // ---- GATE for both half-tiles ----
        float glane[2][4][2];   // [t][m][j]
        const uint4 g1f = *(const uint4*)(sG1frag + lane * 16);
        const uint4 g2f = *(const uint4*)(sG2frag + lane * 16);
        #pragma unroll
        for (int t = 0; t < 2; t++) {
            float hgd[2][4][4];
            #pragma unroll
            for (int nf = 0; nf < 4; nf++) {
                const u32 bh = (nf == 0) ? g1f.x : (nf == 1) ? g1f.y : (nf == 2) ? g1f.z : g1f.w;
                #pragma unroll
                for (int mf = 0; mf < 2; mf++) {
                    mma_f16_k8_c(hgd[mf][nf][0], hgd[mf][nf][1], hgd[mf][nf][2], hgd[mf][nf][3],
                                 xhi[t][mf][0], xhi[t][mf][1], bh, fz, fz, fz, fz);
                }
            }
            u32 ag[2][2][4];
            #pragma unroll
            for (int mf = 0; mf < 2; mf++) {
                #pragma unroll
                for (int nf = 0; nf < 4; nf++) {
                    const int kf = nf >> 1, half = nf & 1;
                    ag[mf][kf][half * 2 + 0] = hmax2z(f16x2_of(hgd[mf][nf][0], hgd[mf][nf][1]));
                    ag[mf][kf][half * 2 + 1] = hmax2z(f16x2_of(hgd[mf][nf][2], hgd[mf][nf][3]));
                }
            }
            float gl[2][4];
            #pragma unroll
            for (int mf = 0; mf < 2; mf++) {
                mma_f16_c(gl[mf][0], gl[mf][1], gl[mf][2], gl[mf][3],
                          ag[mf][0][0], ag[mf][0][1], ag[mf][0][2], ag[mf][0][3],
                          g2f.x, g2f.y,
                          bg2c.x, bg2c.y, bg2c.x, bg2c.y);
                mma_f16(gl[mf][0], gl[mf][1], gl[mf][2], gl[mf][3],
                        ag[mf][1][0], ag[mf][1][1], ag[mf][1][2], ag[mf][1][3],
                        g2f.z, g2f.w);
            }
            #pragma unroll
            for (int mf = 0; mf < 2; mf++) {
                #pragma unroll
                for (int r = 0; r < 2; r++) {
                    const int m = 2 * mf + r;
                    const float l0 = gl[mf][r * 2 + 0];
                    const float l1 = gl[mf][r * 2 + 1];
                    float mx = fmaxf(l0, l1);
                    mx = fmaxf(mx, __shfl_xor_sync(0xffffffffu, mx, 1));
                    mx = fmaxf(mx, __shfl_xor_sync(0xffffffffu, mx, 2));
                    const float e0 = __expf(l0 - mx);
                    const float e1 = __expf(l1 - mx);
                    float s = e0 + e1;
                    s += __shfl_xor_sync(0xffffffffu, s, 1);
                    s += __shfl_xor_sync(0xffffffffu, s, 2);
                    const float inv = 1.0f / s;
                    glane[t][m][0] = e0 * inv;
                    glane[t][m][1] = e1 * inv;
                }
            }
        }

        // persistent layer-3 accumulators for both half-tiles
        float acc[2][2][4];   // [t][mf][reg]

        // ---- experts: fragments loaded once, both half-tiles processed ----
        #pragma unroll
        for (int e = 0; e < ED; e++) {
            const uint4 b1f = *(const uint4*)(sB1frag + (e * 32 + lane) * 16);
            uint4 cH[4];
            #pragma unroll
            for (int c = 0; c < 4; c++)
                cH[c] = *(const uint4*)(sBfrag + ((e * 4 + c) * 32 + lane) * 16);
            float2 b2p[4];
            #pragma unroll
            for (int nf = 0; nf < 4; nf++)
                b2p[nf] = *(const float2*)&sb2[e * HH + nf * 8 + 2 * q];

            #pragma unroll
            for (int t = 0; t < 2; t++) {
                // layer 1
                float h1d[2][4][4];
                #pragma unroll
                for (int nf = 0; nf < 4; nf++) {
                    const u32 bh = (nf == 0) ? b1f.x : (nf == 1) ? b1f.y : (nf == 2) ? b1f.z : b1f.w;
                    #pragma unroll
                    for (int mf = 0; mf < 2; mf++) {
                        mma_f16_k8_c(h1d[mf][nf][0], h1d[mf][nf][1], h1d[mf][nf][2], h1d[mf][nf][3],
                                     xhi[t][mf][0], xhi[t][mf][1], bh, fz, fz, fz, fz);
                    }
                }
                // relu fp16 + pack
                u32 ahi[2][2][4];
                #pragma unroll
                for (int mf = 0; mf < 2; mf++) {
                    #pragma unroll
                    for (int nf = 0; nf < 4; nf++) {
                        const int kf = nf >> 1, half = nf & 1;
                        ahi[mf][kf][half * 2 + 0] = hmax2z(f16x2_of(h1d[mf][nf][0], h1d[mf][nf][1]));
                        ahi[mf][kf][half * 2 + 1] = hmax2z(f16x2_of(h1d[mf][nf][2], h1d[mf][nf][3]));
                    }
                }
                // layer 2
                float dd[2][4][4];
                #pragma unroll
                for (int nf = 0; nf < 4; nf++) {
                    const uint4 h40 = cH[0 * 2 + (nf >> 1)];
                    const uint4 h41 = cH[1 * 2 + (nf >> 1)];
                    const u32 b0k0 = (nf & 1) ? h40.z : h40.x;
                    const u32 b1k0 = (nf & 1) ? h40.w : h40.y;
                    const u32 b0k1 = (nf & 1) ? h41.z : h41.x;
                    const u32 b1k1 = (nf & 1) ? h41.w : h41.y;
                    #pragma unroll
                    for (int mf = 0; mf < 2; mf++) {
                        mma_f16_c(dd[mf][nf][0], dd[mf][nf][1], dd[mf][nf][2], dd[mf][nf][3],
                                  ahi[mf][0][0], ahi[mf][0][1], ahi[mf][0][2], ahi[mf][0][3],
                                  b0k0, b1k0,
                                  b2p[nf].x, b2p[nf].y, b2p[nf].x, b2p[nf].y);
                        mma_f16(dd[mf][nf][0], dd[mf][nf][1], dd[mf][nf][2], dd[mf][nf][3],
                                ahi[mf][1][0], ahi[mf][1][1], ahi[mf][1][2], ahi[mf][1][3],
                                b0k1, b1k1);
                    }
                }
                // gate scale + relu fp16
                u32 geh[4];
                #pragma unroll
                for (int m = 0; m < 4; m++) {
                    const float ge = __shfl_sync(0xffffffffu, glane[t][m][e & 1], (lane & 28) + (e >> 1));
                    geh[m] = f16x2_of(ge, ge);
                }
                u32 a3[2][2][4];
                #pragma unroll
                for (int mf = 0; mf < 2; mf++) {
                    #pragma unroll
                    for (int nf = 0; nf < 4; nf++) {
                        const int kf = nf >> 1, half = nf & 1;
                        a3[mf][kf][half * 2 + 0] =
                            hmul2(hmax2z(f16x2_of(dd[mf][nf][0], dd[mf][nf][1])), geh[2 * mf + 0]);
                        a3[mf][kf][half * 2 + 1] =
                            hmul2(hmax2z(f16x2_of(dd[mf][nf][2], dd[mf][nf][3])), geh[2 * mf + 1]);
                    }
                }
                // layer 3, accumulated across experts
                #pragma unroll
                for (int mf = 0; mf < 2; mf++) {
                    if (e == 0) {
                        mma_f16_c(acc[t][mf][0], acc[t][mf][1], acc[t][mf][2], acc[t][mf][3],
                                  a3[mf][0][0], a3[mf][0][1], a3[mf][0][2], a3[mf][0][3],
                                  w3f[e][0], w3f[e][1], fz, fz, fz, fz);
                    } else {
                        mma_f16(acc[t][mf][0], acc[t][mf][1], acc[t][mf][2], acc[t][mf][3],
                                a3[mf][0][0], a3[mf][0][1], a3[mf][0][2], a3[mf][0][3],
                                w3f[e][0], w3f[e][1]);
                    }
                    mma_f16(acc[t][mf][0], acc[t][mf][1], acc[t][mf][2], acc[t][mf][3],
                            a3[mf][1][0], a3[mf][1][1], a3[mf][1][2], a3[mf][1][3],
                            w3f[e][2], w3f[e][3]);
                }
            }
        }

        // ---- b3 tail + store per half-tile ----
        #pragma unroll
        for (int t = 0; t < 2; t++) {
            u64 bias[4];
            #pragma unroll
            for (int m = 0; m < 4; m++) {
                u64 p = mul2(pack_dup(glane[t][m][0]), b3q0);
                ffma2_acc(p, pack_dup(glane[t][m][1]), b3q1);
                p = add2(p, __shfl_xor_sync(0xffffffffu, p, 1));
                p = add2(p, __shfl_xor_sync(0xffffffffu, p, 2));
                bias[m] = p;
            }
            if (q == 0) {
                const float2 bb0 = unpack2(bias[0]);
                const float2 bb1 = unpack2(bias[1]);
                const float2 bb2 = unpack2(bias[2]);
                const float2 bb3 = unpack2(bias[3]);
                const int t0 = base + t * 32 + g;
                if (t0 < B)      ((float2*)gout)[t0]      = make_float2(acc[t][0][0] + bb0.x, acc[t][0][1] + bb0.y);
                if (t0 + 8 < B)  ((float2*)gout)[t0 + 8]  = make_float2(acc[t][0][2] + bb1.x, acc[t][0][3] + bb1.y);
                if (t0 + 16 < B) ((float2*)gout)[t0 + 16] = make_float2(acc[t][1][0] + bb2.x, acc[t][1][1] + bb2.y);
                if (t0 + 24 < B) ((float2*)gout)[t0 + 24] = make_float2(acc[t][1][2] + bb3.x, acc[t][1][3] + bb3.y);
            }
        }
    }
}

extern "C" void kernel_launch(void* const* d_in, const int* in_sizes, int n_in,
                              void* d_out, int out_size)
{
    const float* x   = (const float*)d_in[0];
    const float* W1  = (const float*)d_in[1];
    const float* b1  = (const float*)d_in[2];
    const float* W2  = (const float*)d_in[3];
    const float* b2  = (const float*)d_in[4];
    const float* W3  = (const float*)d_in[5];
    const float* b3  = (const float*)d_in[6];
    const float* Wg1 = (const float*)d_in[7];
    const float* bg1 = (const float*)d_in[8];
    const float* Wg2 = (const float*)d_in[9];
    const float* bg2 = (const float*)d_in[10];
    float* out = (float*)d_out;

    const int B  = in_sizes[0] / DI;
    const int NT = (B + 255) / 256;

    int nsm = 148;
    cudaDeviceGetAttribute(&nsm, cudaDevAttrMultiProcessorCount, 0);
    int grid = 2 * nsm;
    if (grid > NT) grid = NT;

    moe_mma_kernel<<<grid, 128>>>(x, W1, b1, W2, b2, W3, b3,
                                  Wg1, bg1, Wg2, bg2, out, B, NT);
}

// round 16
// speedup vs baseline: 1.1491x; 1.1491x over previous
#include <cuda_runtime.h>
#include <cuda_fp16.h>
#include <cstdint>

// MoE dense 8-expert: D_IN=6, H=32, D_OUT=2, B=1M, fp32.
// R16 = R14 (all four GEMMs fp16 mma.sync, 3 CTAs/SM, 32 tok/warp) with:
//  - layer-1 + gate-layer-1 use f16-accumulator HMMA (single MMA => one
//    rounding at writeback, same math as f32-D + cvt) -> D arrives packed in
//    layer-2 A-frag layout; deletes ~144 cvt ops/tile.
//  - gate broadcast packed: one f16x2 shfl per expert PAIR + one PRMT dup per
//    expert (replaces 2 shfl + 2 cvt per pair).

#define ED 8
#define DI 6
#define HH 32
#define DO 2

typedef unsigned long long u64;
typedef unsigned int u32;

__device__ __forceinline__ u32 f16x2_of(float lo_e, float hi_e) {
    u32 r; asm("cvt.rn.f16x2.f32 %0, %1, %2;" : "=r"(r) : "f"(hi_e), "f"(lo_e)); return r;
}
__device__ __forceinline__ u32 hmax2z(u32 a) {
    u32 r; asm("max.f16x2 %0, %1, %2;" : "=r"(r) : "r"(a), "r"(0u)); return r;
}
__device__ __forceinline__ u32 hmul2(u32 a, u32 b) {
    u32 r; asm("mul.f16x2 %0, %1, %2;" : "=r"(r) : "r"(a), "r"(b)); return r;
}
__device__ __forceinline__ u32 prmt_sel(u32 a, u32 sel) {
    u32 r; asm("prmt.b32 %0, %1, %2, %3;" : "=r"(r) : "r"(a), "r"(0u), "r"(sel)); return r;
}
__device__ __forceinline__ void ffma2_acc(u64& acc, u64 a, u64 b) {
    asm("fma.rn.f32x2 %0, %1, %2, %0;" : "+l"(acc) : "l"(a), "l"(b));
}
__device__ __forceinline__ u64 mul2(u64 a, u64 b) {
    u64 r; asm("mul.rn.f32x2 %0, %1, %2;" : "=l"(r) : "l"(a), "l"(b)); return r;
}
__device__ __forceinline__ u64 add2(u64 a, u64 b) {
    u64 r; asm("add.rn.f32x2 %0, %1, %2;" : "=l"(r) : "l"(a), "l"(b)); return r;
}
__device__ __forceinline__ u64 pack_dup(float v) {
    u64 r; asm("mov.b64 %0, {%1, %1};" : "=l"(r) : "r"(__float_as_uint(v))); return r;
}
__device__ __forceinline__ float2 unpack2(u64 v) {
    float2 f; asm("mov.b64 {%0, %1}, %2;" : "=f"(f.x), "=f"(f.y) : "l"(v)); return f;
}

// ---- MMA helpers ----
__device__ __forceinline__ void mma_f16(float& d0, float& d1, float& d2, float& d3,
                                        u32 a0, u32 a1, u32 a2, u32 a3,
                                        u32 b0, u32 b1) {
    asm("mma.sync.aligned.m16n8k16.row.col.f32.f16.f16.f32 "
        "{%0,%1,%2,%3}, {%4,%5,%6,%7}, {%8,%9}, {%0,%1,%2,%3};"
        : "+f"(d0), "+f"(d1), "+f"(d2), "+f"(d3)
        : "r"(a0), "r"(a1), "r"(a2), "r"(a3), "r"(b0), "r"(b1));
}
__device__ __forceinline__ void mma_f16_c(float& d0, float& d1, float& d2, float& d3,
                                          u32 a0, u32 a1, u32 a2, u32 a3,
                                          u32 b0, u32 b1,
                                          float c0, float c1, float c2, float c3) {
    asm("mma.sync.aligned.m16n8k16.row.col.f32.f16.f16.f32 "
        "{%0,%1,%2,%3}, {%4,%5,%6,%7}, {%8,%9}, {%10,%11,%12,%13};"
        : "=f"(d0), "=f"(d1), "=f"(d2), "=f"(d3)
        : "r"(a0), "r"(a1), "r"(a2), "r"(a3), "r"(b0), "r"(b1),
          "f"(c0), "f"(c1), "f"(c2), "f"(c3));
}
// k8 MMA with f16 accumulator/output (D packed as f16x2: reg0 = rows g, reg1 = rows g+8)
__device__ __forceinline__ void mma_f16_k8_h16(u32& d0, u32& d1,
                                               u32 a0, u32 a1, u32 b0) {
    asm("mma.sync.aligned.m16n8k8.row.col.f16.f16.f16.f16 "
        "{%0,%1}, {%2,%3}, {%4}, {%5,%6};"
        : "=r"(d0), "=r"(d1)
        : "r"(a0), "r"(a1), "r"(b0), "r"(0u), "r"(0u));
}

__global__ __launch_bounds__(128, 3)
void moe_mma_kernel(const float* __restrict__ gx,
                    const float* __restrict__ gW1, const float* __restrict__ gb1,
                    const float* __restrict__ gW2, const float* __restrict__ gb2,
                    const float* __restrict__ gW3, const float* __restrict__ gb3,
                    const float* __restrict__ gWg1, const float* __restrict__ gbg1,
                    const float* __restrict__ gWg2, const float* __restrict__ gbg2,
                    float* __restrict__ gout, int B, int NT)
{
    __shared__ __align__(16) float sx[4 * 192];               // per-warp x tiles
    __shared__ __align__(16) char  sBfrag[ED * 4 * 32 * 16];  // layer-2 W2 fp16 frags
    __shared__ __align__(16) char  sB1frag[ED * 32 * 16];     // layer-1 W1 fp16 frags, b1 @k=6
    __shared__ __align__(16) char  sG1frag[32 * 16];          // gate Wg1 frag, bg1 @k=6
    __shared__ __align__(16) char  sG2frag[32 * 16];          // gate Wg2 frag (K=32, N=8)
    __shared__ __align__(16) float sb2[ED * HH];

    const int tid  = threadIdx.x;
    const int w    = tid >> 5;
    const int lane = tid & 31;
    const int g    = lane >> 2;   // groupID
    const int q    = lane & 3;    // threadID in group

    for (int i = tid; i < ED * HH; i += 128) sb2[i] = gb2[i];

    // ---- precompute per-lane B fragments (fp16) ----
    for (int e = w * 2; e < w * 2 + 2; e++) {
        #pragma unroll
        for (int c = 0; c < 4; c++) {
            const int kf = c >> 1, nfh = c & 1;
            u32 hi4[4];
            #pragma unroll
            for (int p = 0; p < 2; p++) {
                const int n  = (nfh * 2 + p) * 8 + g;
                const int k0 = kf * 16 + 2 * q;
                hi4[p * 2 + 0] = f16x2_of(gW2[e * 1024 + (k0    ) * 32 + n],
                                          gW2[e * 1024 + (k0 + 1) * 32 + n]);
                hi4[p * 2 + 1] = f16x2_of(gW2[e * 1024 + (k0 + 8) * 32 + n],
                                          gW2[e * 1024 + (k0 + 9) * 32 + n]);
            }
            *(uint4*)(sBfrag + ((e * 4 + c) * 32 + lane) * 16) = make_uint4(hi4[0], hi4[1], hi4[2], hi4[3]);
        }
        {
            u32 hi4[4];
            #pragma unroll
            for (int nf = 0; nf < 4; nf++) {
                const int n = nf * 8 + g;
                float w0, w1;
                if (q < 3) {
                    w0 = gW1[e * 192 + (2 * q    ) * 32 + n];
                    w1 = gW1[e * 192 + (2 * q + 1) * 32 + n];
                } else {
                    w0 = gb1[e * 32 + n];
                    w1 = 0.0f;
                }
                hi4[nf] = f16x2_of(w0, w1);
            }
            *(uint4*)(sB1frag + (e * 32 + lane) * 16) = make_uint4(hi4[0], hi4[1], hi4[2], hi4[3]);
        }
    }
    if (w == 0) {
        u32 hi4[4];
        #pragma unroll
        for (int nf = 0; nf < 4; nf++) {
            const int n = nf * 8 + g;
            float w0, w1;
            if (q < 3) {
                w0 = gWg1[(2 * q    ) * 32 + n];
                w1 = gWg1[(2 * q + 1) * 32 + n];
            } else {
                w0 = gbg1[n];
                w1 = 0.0f;
            }
            hi4[nf] = f16x2_of(w0, w1);
        }
        *(uint4*)(sG1frag + lane * 16) = make_uint4(hi4[0], hi4[1], hi4[2], hi4[3]);
    }
    if (w == 1) {
        u32 f4[4];
        #pragma unroll
        for (int kf = 0; kf < 2; kf++) {
            const int k0 = kf * 16 + 2 * q;
            f4[kf * 2 + 0] = f16x2_of(gWg2[(k0    ) * ED + g], gWg2[(k0 + 1) * ED + g]);
            f4[kf * 2 + 1] = f16x2_of(gWg2[(k0 + 8) * ED + g], gWg2[(k0 + 9) * ED + g]);
        }
        *(uint4*)(sG2frag + lane * 16) = make_uint4(f4[0], f4[1], f4[2], f4[3]);
    }
    __syncthreads();

    // ---- layer-3 W3 B-fragments in registers (K=32, N=8; cols>=2 zero) ----
    u32 w3f[ED][4];
    #pragma unroll
    for (int e = 0; e < ED; e++) {
        #pragma unroll
        for (int kf = 0; kf < 2; kf++) {
            const int k0 = kf * 16 + 2 * q;
            u32 b0 = 0, b1 = 0;
            if (g < 2) {
                b0 = f16x2_of(gW3[e * 64 + (k0    ) * DO + g], gW3[e * 64 + (k0 + 1) * DO + g]);
                b1 = f16x2_of(gW3[e * 64 + (k0 + 8) * DO + g], gW3[e * 64 + (k0 + 9) * DO + g]);
            }
            w3f[e][kf * 2 + 0] = b0;
            w3f[e][kf * 2 + 1] = b1;
        }
    }
    const u64 b3q0 = *(const u64*)&gb3[(2 * q    ) * DO];
    const u64 b3q1 = *(const u64*)&gb3[(2 * q + 1) * DO];

    const int lim6 = B * DI;
    const float fz = 0.0f;
    const float2 bg2c = ((const float2*)gbg2)[q];

    // ---- persistent per-warp tile loop (32 tokens per warp) ----
    for (int tile = blockIdx.x; tile < NT; tile += gridDim.x) {
        const int base = tile * 128 + w * 32;
        float* sxw = sx + w * 192;
        #pragma unroll
        for (int i = 0; i < 6; i++) {
            const int idx = base * DI + i * 32 + lane;
            sxw[i * 32 + lane] = (idx < lim6) ? gx[idx] : 0.0f;
        }
        __syncwarp();

        // ---- x A-fragments (fp16, k8 layout); q==3 -> 1.0 bias slot ----
        u32 xhi[2][2];
        #pragma unroll
        for (int mf = 0; mf < 2; mf++) {
            const int r0 = 16 * mf + g, r1 = r0 + 8;
            float v00, v01, v10, v11;
            if (q < 3) {
                v00 = sxw[r0 * DI + 2 * q]; v01 = sxw[r0 * DI + 2 * q + 1];
                v10 = sxw[r1 * DI + 2 * q]; v11 = sxw[r1 * DI + 2 * q + 1];
            } else {
                v00 = 1.0f; v01 = 0.0f; v10 = 1.0f; v11 = 0.0f;
            }
            xhi[mf][0] = f16x2_of(v00, v01);
            xhi[mf][1] = f16x2_of(v10, v11);
        }

        // ---- GATE via MMA (f16-D layer-1) + quad-butterfly softmax ----
        float glane[4][2];   // f32 gates (for b3 tail)
        u32 ghp[4];          // packed f16x2 gates {expert 2q, expert 2q+1} per row m
        {
            const uint4 g1f = *(const uint4*)(sG1frag + lane * 16);
            u32 ag[2][2][4];
            #pragma unroll
            for (int nf = 0; nf < 4; nf++) {
                const u32 bh = (nf == 0) ? g1f.x : (nf == 1) ? g1f.y : (nf == 2) ? g1f.z : g1f.w;
                const int kf = nf >> 1, half = nf & 1;
                #pragma unroll
                for (int mf = 0; mf < 2; mf++) {
                    u32 p0, p1;
                    mma_f16_k8_h16(p0, p1, xhi[mf][0], xhi[mf][1], bh);
                    ag[mf][kf][half * 2 + 0] = hmax2z(p0);
                    ag[mf][kf][half * 2 + 1] = hmax2z(p1);
                }
            }
            const uint4 g2f = *(const uint4*)(sG2frag + lane * 16);
            float gl[2][4];
            #pragma unroll
            for (int mf = 0; mf < 2; mf++) {
                mma_f16_c(gl[mf][0], gl[mf][1], gl[mf][2], gl[mf][3],
                          ag[mf][0][0], ag[mf][0][1], ag[mf][0][2], ag[mf][0][3],
                          g2f.x, g2f.y,
                          bg2c.x, bg2c.y, bg2c.x, bg2c.y);
                mma_f16(gl[mf][0], gl[mf][1], gl[mf][2], gl[mf][3],
                        ag[mf][1][0], ag[mf][1][1], ag[mf][1][2], ag[mf][1][3],
                        g2f.z, g2f.w);
            }
            #pragma unroll
            for (int mf = 0; mf < 2; mf++) {
                #pragma unroll
                for (int r = 0; r < 2; r++) {
                    const int m = 2 * mf + r;
                    const float l0 = gl[mf][r * 2 + 0];
                    const float l1 = gl[mf][r * 2 + 1];
                    float mx = fmaxf(l0, l1);
                    mx = fmaxf(mx, __shfl_xor_sync(0xffffffffu, mx, 1));
                    mx = fmaxf(mx, __shfl_xor_sync(0xffffffffu, mx, 2));
                    const float e0 = __expf(l0 - mx);
                    const float e1 = __expf(l1 - mx);
                    float s = e0 + e1;
                    s += __shfl_xor_sync(0xffffffffu, s, 1);
                    s += __shfl_xor_sync(0xffffffffu, s, 2);
                    const float inv = 1.0f / s;
                    glane[m][0] = e0 * inv;
                    glane[m][1] = e1 * inv;
                    ghp[m] = f16x2_of(glane[m][0], glane[m][1]);
                }
            }
        }

        float acc[2][4];   // persistent layer-3 accumulator
        u32 gsh[4];        // packed gate pair fetched per expert-pair

        // ---- experts ----
        #pragma unroll
        for (int e = 0; e < ED; e++) {
            const uint4 b1f = *(const uint4*)(sB1frag + (e * 32 + lane) * 16);
            uint4 cH[4];
            #pragma unroll
            for (int c = 0; c < 4; c++)
                cH[c] = *(const uint4*)(sBfrag + ((e * 4 + c) * 32 + lane) * 16);

            // layer 1: ONE f16-D k8 MMA per (nf,mf) -> packed A-frags directly
            u32 ahi[2][2][4];
            #pragma unroll
            for (int nf = 0; nf < 4; nf++) {
                const u32 bh = (nf == 0) ? b1f.x : (nf == 1) ? b1f.y : (nf == 2) ? b1f.z : b1f.w;
                const int kf = nf >> 1, half = nf & 1;
                #pragma unroll
                for (int mf = 0; mf < 2; mf++) {
                    u32 p0, p1;
                    mma_f16_k8_h16(p0, p1, xhi[mf][0], xhi[mf][1], bh);
                    ahi[mf][kf][half * 2 + 0] = hmax2z(p0);
                    ahi[mf][kf][half * 2 + 1] = hmax2z(p1);
                }
            }

            // b2 bias fragments
            float2 b2p[4];
            #pragma unroll
            for (int nf = 0; nf < 4; nf++)
                b2p[nf] = *(const float2*)&sb2[e * HH + nf * 8 + 2 * q];

            // layer-2: TWO k16 MMAs per (nf,mf); b2 via C on the first (f32 D)
            float dd[2][4][4];
            #pragma unroll
            for (int nf = 0; nf < 4; nf++) {
                const uint4 h40 = cH[0 * 2 + (nf >> 1)];
                const uint4 h41 = cH[1 * 2 + (nf >> 1)];
                const u32 b0k0 = (nf & 1) ? h40.z : h40.x;
                const u32 b1k0 = (nf & 1) ? h40.w : h40.y;
                const u32 b0k1 = (nf & 1) ? h41.z : h41.x;
                const u32 b1k1 = (nf & 1) ? h41.w : h41.y;
                #pragma unroll
                for (int mf = 0; mf < 2; mf++) {
                    mma_f16_c(dd[mf][nf][0], dd[mf][nf][1], dd[mf][nf][2], dd[mf][nf][3],
                              ahi[mf][0][0], ahi[mf][0][1], ahi[mf][0][2], ahi[mf][0][3],
                              b0k0, b1k0,
                              b2p[nf].x, b2p[nf].y, b2p[nf].x, b2p[nf].y);
                    mma_f16(dd[mf][nf][0], dd[mf][nf][1], dd[mf][nf][2], dd[mf][nf][3],
                            ahi[mf][1][0], ahi[mf][1][1], ahi[mf][1][2], ahi[mf][1][3],
                            b0k1, b1k1);
                }
            }

            // gate per row: one packed shfl per expert-pair, PRMT dup per expert
            if ((e & 1) == 0) {
                #pragma unroll
                for (int m = 0; m < 4; m++)
                    gsh[m] = __shfl_sync(0xffffffffu, ghp[m], (lane & 28) + (e >> 1));
            }
            const u32 dupsel = (e & 1) ? 0x3232u : 0x1010u;
            u32 geh[4];
            #pragma unroll
            for (int m = 0; m < 4; m++) geh[m] = prmt_sel(gsh[m], dupsel);

            // layer-3 A frags: relu(dd) in fp16 scaled by gate
            u32 a3[2][2][4];
            #pragma unroll
            for (int mf = 0; mf < 2; mf++) {
                #pragma unroll
                for (int nf = 0; nf < 4; nf++) {
                    const int kf = nf >> 1, half = nf & 1;
                    a3[mf][kf][half * 2 + 0] =
                        hmul2(hmax2z(f16x2_of(dd[mf][nf][0], dd[mf][nf][1])), geh[2 * mf + 0]);
                    a3[mf][kf][half * 2 + 1] =
                        hmul2(hmax2z(f16x2_of(dd[mf][nf][2], dd[mf][nf][3])), geh[2 * mf + 1]);
                }
            }

            // layer-3 MMAs, accumulating across experts (C=0 on very first)
            #pragma unroll
            for (int mf = 0; mf < 2; mf++) {
                if (e == 0) {
                    mma_f16_c(acc[mf][0], acc[mf][1], acc[mf][2], acc[mf][3],
                              a3[mf][0][0], a3[mf][0][1], a3[mf][0][2], a3[mf][0][3],
                              w3f[e][0], w3f[e][1], fz, fz, fz, fz);
                } else {
                    mma_f16(acc[mf][0], acc[mf][1], acc[mf][2], acc[mf][3],
                            a3[mf][0][0], a3[mf][0][1], a3[mf][0][2], a3[mf][0][3],
                            w3f[e][0], w3f[e][1]);
                }
                mma_f16(acc[mf][0], acc[mf][1], acc[mf][2], acc[mf][3],
                        a3[mf][1][0], a3[mf][1][1], a3[mf][1][2], a3[mf][1][3],
                        w3f[e][2], w3f[e][3]);
            }
        }

        // ---- b3 tail: bias[m] = sum_e g[row][e]*b3[e][:], via quad butterflies ----
        u64 bias[4];
        #pragma unroll
        for (int m = 0; m < 4; m++) {
            u64 p = mul2(pack_dup(glane[m][0]), b3q0);
            ffma2_acc(p, pack_dup(glane[m][1]), b3q1);
            p = add2(p, __shfl_xor_sync(0xffffffffu, p, 1));
            p = add2(p, __shfl_xor_sync(0xffffffffu, p, 2));
            bias[m] = p;
        }

        // ---- store: q==0 lanes hold cols 0,1 for rows g+8m ----
        if (q == 0) {
            const float2 bb0 = unpack2(bias[0]);
            const float2 bb1 = unpack2(bias[1]);
            const float2 bb2 = unpack2(bias[2]);
            const float2 bb3 = unpack2(bias[3]);
            const int t0 = base + g;
            if (t0 < B)      ((float2*)gout)[t0]      = make_float2(acc[0][0] + bb0.x, acc[0][1] + bb0.y);
            if (t0 + 8 < B)  ((float2*)gout)[t0 + 8]  = make_float2(acc[0][2] + bb1.x, acc[0][3] + bb1.y);
            if (t0 + 16 < B) ((float2*)gout)[t0 + 16] = make_float2(acc[1][0] + bb2.x, acc[1][1] + bb2.y);
            if (t0 + 24 < B) ((float2*)gout)[t0 + 24] = make_float2(acc[1][2] + bb3.x, acc[1][3] + bb3.y);
        }
    }
}

extern "C" void kernel_launch(void* const* d_in, const int* in_sizes, int n_in,
                              void* d_out, int out_size)
{
    const float* x   = (const float*)d_in[0];
    const float* W1  = (const float*)d_in[1];
    const float* b1  = (const float*)d_in[2];
    const float* W2  = (const float*)d_in[3];
    const float* b2  = (const float*)d_in[4];
    const float* W3  = (const float*)d_in[5];
    const float* b3  = (const float*)d_in[6];
    const float* Wg1 = (const float*)d_in[7];
    const float* bg1 = (const float*)d_in[8];
    const float* Wg2 = (const float*)d_in[9];
    const float* bg2 = (const float*)d_in[10];
    float* out = (float*)d_out;

    const int B  = in_sizes[0] / DI;
    const int NT = (B + 127) / 128;

    int nsm = 148;
    cudaDeviceGetAttribute(&nsm, cudaDevAttrMultiProcessorCount, 0);
    int grid = 3 * nsm;          // 3 CTAs/SM (R14 best config)
    if (grid > NT) grid = NT;

    moe_mma_kernel<<<grid, 128>>>(x, W1, b1, W2, b2, W3, b3,
                                  Wg1, bg1, Wg2, bg2, out, B, NT);
}

// round 17
// speedup vs baseline: 1.2115x; 1.0544x over previous
#include <cuda_runtime.h>
#include <cuda_fp16.h>
#include <cstdint>

// MoE dense 8-expert: D_IN=6, H=32, D_OUT=2, B=1M, fp32.
// R17 = R16 with layer-2 on f16-accumulator chained HMMA:
//  - layer-2's two k16 MMAs produce packed f16 D (first MMA C = pre-packed
//    f16x2 b2 frag, second accumulates in place). D lands directly in the
//    layer-3 A-operand layout -> deletes 128 cvt/tile and halves dd regs.
//  - b2 frags packed once into smem as [e][q][nf] uint4 (one LDS.128/expert).
// Layer-1/gate-layer-1 f16-D (R16), gate-layer-2 + layer-3 keep f32 D.
// 3 CTAs/SM, 32 tok/warp.

#define ED 8
#define DI 6
#define HH 32
#define DO 2

typedef unsigned long long u64;
typedef unsigned int u32;

__device__ __forceinline__ u32 f16x2_of(float lo_e, float hi_e) {
    u32 r; asm("cvt.rn.f16x2.f32 %0, %1, %2;" : "=r"(r) : "f"(hi_e), "f"(lo_e)); return r;
}
__device__ __forceinline__ u32 hmax2z(u32 a) {
    u32 r; asm("max.f16x2 %0, %1, %2;" : "=r"(r) : "r"(a), "r"(0u)); return r;
}
__device__ __forceinline__ u32 hmul2(u32 a, u32 b) {
    u32 r; asm("mul.f16x2 %0, %1, %2;" : "=r"(r) : "r"(a), "r"(b)); return r;
}
__device__ __forceinline__ u32 prmt_sel(u32 a, u32 sel) {
    u32 r; asm("prmt.b32 %0, %1, %2, %3;" : "=r"(r) : "r"(a), "r"(0u), "r"(sel)); return r;
}
__device__ __forceinline__ void ffma2_acc(u64& acc, u64 a, u64 b) {
    asm("fma.rn.f32x2 %0, %1, %2, %0;" : "+l"(acc) : "l"(a), "l"(b));
}
__device__ __forceinline__ u64 mul2(u64 a, u64 b) {
    u64 r; asm("mul.rn.f32x2 %0, %1, %2;" : "=l"(r) : "l"(a), "l"(b)); return r;
}
__device__ __forceinline__ u64 add2(u64 a, u64 b) {
    u64 r; asm("add.rn.f32x2 %0, %1, %2;" : "=l"(r) : "l"(a), "l"(b)); return r;
}
__device__ __forceinline__ u64 pack_dup(float v) {
    u64 r; asm("mov.b64 %0, {%1, %1};" : "=l"(r) : "r"(__float_as_uint(v))); return r;
}
__device__ __forceinline__ float2 unpack2(u64 v) {
    float2 f; asm("mov.b64 {%0, %1}, %2;" : "=f"(f.x), "=f"(f.y) : "l"(v)); return f;
}

// ---- MMA helpers ----
__device__ __forceinline__ void mma_f16(float& d0, float& d1, float& d2, float& d3,
                                        u32 a0, u32 a1, u32 a2, u32 a3,
                                        u32 b0, u32 b1) {
    asm("mma.sync.aligned.m16n8k16.row.col.f32.f16.f16.f32 "
        "{%0,%1,%2,%3}, {%4,%5,%6,%7}, {%8,%9}, {%0,%1,%2,%3};"
        : "+f"(d0), "+f"(d1), "+f"(d2), "+f"(d3)
        : "r"(a0), "r"(a1), "r"(a2), "r"(a3), "r"(b0), "r"(b1));
}
__device__ __forceinline__ void mma_f16_c(float& d0, float& d1, float& d2, float& d3,
                                          u32 a0, u32 a1, u32 a2, u32 a3,
                                          u32 b0, u32 b1,
                                          float c0, float c1, float c2, float c3) {
    asm("mma.sync.aligned.m16n8k16.row.col.f32.f16.f16.f32 "
        "{%0,%1,%2,%3}, {%4,%5,%6,%7}, {%8,%9}, {%10,%11,%12,%13};"
        : "=f"(d0), "=f"(d1), "=f"(d2), "=f"(d3)
        : "r"(a0), "r"(a1), "r"(a2), "r"(a3), "r"(b0), "r"(b1),
          "f"(c0), "f"(c1), "f"(c2), "f"(c3));
}
// k8 MMA with f16 accumulator/output
__device__ __forceinline__ void mma_f16_k8_h16(u32& d0, u32& d1,
                                               u32 a0, u32 a1, u32 b0) {
    asm("mma.sync.aligned.m16n8k8.row.col.f16.f16.f16.f16 "
        "{%0,%1}, {%2,%3}, {%4}, {%5,%6};"
        : "=r"(d0), "=r"(d1)
        : "r"(a0), "r"(a1), "r"(b0), "r"(0u), "r"(0u));
}
// k16 MMA with f16 accumulator, explicit C
__device__ __forceinline__ void mma_f16_k16_h16_c(u32& d0, u32& d1,
                                                  u32 a0, u32 a1, u32 a2, u32 a3,
                                                  u32 b0, u32 b1, u32 c0, u32 c1) {
    asm("mma.sync.aligned.m16n8k16.row.col.f16.f16.f16.f16 "
        "{%0,%1}, {%2,%3,%4,%5}, {%6,%7}, {%8,%9};"
        : "=r"(d0), "=r"(d1)
        : "r"(a0), "r"(a1), "r"(a2), "r"(a3), "r"(b0), "r"(b1), "r"(c0), "r"(c1));
}
// k16 MMA with f16 accumulator, in-place accumulate
__device__ __forceinline__ void mma_f16_k16_h16_acc(u32& d0, u32& d1,
                                                    u32 a0, u32 a1, u32 a2, u32 a3,
                                                    u32 b0, u32 b1) {
    asm("mma.sync.aligned.m16n8k16.row.col.f16.f16.f16.f16 "
        "{%0,%1}, {%2,%3,%4,%5}, {%6,%7}, {%0,%1};"
        : "+r"(d0), "+r"(d1)
        : "r"(a0), "r"(a1), "r"(a2), "r"(a3), "r"(b0), "r"(b1));
}

__global__ __launch_bounds__(128, 3)
void moe_mma_kernel(const float* __restrict__ gx,
                    const float* __restrict__ gW1, const float* __restrict__ gb1,
                    const float* __restrict__ gW2, const float* __restrict__ gb2,
                    const float* __restrict__ gW3, const float* __restrict__ gb3,
                    const float* __restrict__ gWg1, const float* __restrict__ gbg1,
                    const float* __restrict__ gWg2, const float* __restrict__ gbg2,
                    float* __restrict__ gout, int B, int NT)
{
    __shared__ __align__(16) float sx[4 * 192];               // per-warp x tiles
    __shared__ __align__(16) char  sBfrag[ED * 4 * 32 * 16];  // layer-2 W2 fp16 frags
    __shared__ __align__(16) char  sB1frag[ED * 32 * 16];     // layer-1 W1 fp16 frags, b1 @k=6
    __shared__ __align__(16) char  sG1frag[32 * 16];          // gate Wg1 frag, bg1 @k=6
    __shared__ __align__(16) char  sG2frag[32 * 16];          // gate Wg2 frag (K=32, N=8)
    __shared__ __align__(16) u32   sb2h[ED * 4 * 4];          // b2 f16x2 frags [e][q][nf]

    const int tid  = threadIdx.x;
    const int w    = tid >> 5;
    const int lane = tid & 31;
    const int g    = lane >> 2;   // groupID
    const int q    = lane & 3;    // threadID in group

    // ---- b2 packed f16x2 fragments: [e][q][nf] ----
    for (int idx = tid; idx < ED * 4; idx += 128) {
        const int e = idx >> 2, qq = idx & 3;
        #pragma unroll
        for (int nf = 0; nf < 4; nf++) {
            sb2h[(e * 4 + qq) * 4 + nf] =
                f16x2_of(gb2[e * HH + nf * 8 + 2 * qq], gb2[e * HH + nf * 8 + 2 * qq + 1]);
        }
    }

    // ---- precompute per-lane B fragments (fp16) ----
    for (int e = w * 2; e < w * 2 + 2; e++) {
        #pragma unroll
        for (int c = 0; c < 4; c++) {
            const int kf = c >> 1, nfh = c & 1;
            u32 hi4[4];
            #pragma unroll
            for (int p = 0; p < 2; p++) {
                const int n  = (nfh * 2 + p) * 8 + g;
                const int k0 = kf * 16 + 2 * q;
                hi4[p * 2 + 0] = f16x2_of(gW2[e * 1024 + (k0    ) * 32 + n],
                                          gW2[e * 1024 + (k0 + 1) * 32 + n]);
                hi4[p * 2 + 1] = f16x2_of(gW2[e * 1024 + (k0 + 8) * 32 + n],
                                          gW2[e * 1024 + (k0 + 9) * 32 + n]);
            }
            *(uint4*)(sBfrag + ((e * 4 + c) * 32 + lane) * 16) = make_uint4(hi4[0], hi4[1], hi4[2], hi4[3]);
        }
        {
            u32 hi4[4];
            #pragma unroll
            for (int nf = 0; nf < 4; nf++) {
                const int n = nf * 8 + g;
                float w0, w1;
                if (q < 3) {
                    w0 = gW1[e * 192 + (2 * q    ) * 32 + n];
                    w1 = gW1[e * 192 + (2 * q + 1) * 32 + n];
                } else {
                    w0 = gb1[e * 32 + n];
                    w1 = 0.0f;
                }
                hi4[nf] = f16x2_of(w0, w1);
            }
            *(uint4*)(sB1frag + (e * 32 + lane) * 16) = make_uint4(hi4[0], hi4[1], hi4[2], hi4[3]);
        }
    }
    if (w == 0) {
        u32 hi4[4];
        #pragma unroll
        for (int nf = 0; nf < 4; nf++) {
            const int n = nf * 8 + g;
            float w0, w1;
            if (q < 3) {
                w0 = gWg1[(2 * q    ) * 32 + n];
                w1 = gWg1[(2 * q + 1) * 32 + n];
            } else {
                w0 = gbg1[n];
                w1 = 0.0f;
            }
            hi4[nf] = f16x2_of(w0, w1);
        }
        *(uint4*)(sG1frag + lane * 16) = make_uint4(hi4[0], hi4[1], hi4[2], hi4[3]);
    }
    if (w == 1) {
        u32 f4[4];
        #pragma unroll
        for (int kf = 0; kf < 2; kf++) {
            const int k0 = kf * 16 + 2 * q;
            f4[kf * 2 + 0] = f16x2_of(gWg2[(k0    ) * ED + g], gWg2[(k0 + 1) * ED + g]);
            f4[kf * 2 + 1] = f16x2_of(gWg2[(k0 + 8) * ED + g], gWg2[(k0 + 9) * ED + g]);
        }
        *(uint4*)(sG2frag + lane * 16) = make_uint4(f4[0], f4[1], f4[2], f4[3]);
    }
    __syncthreads();

    // ---- layer-3 W3 B-fragments in registers (K=32, N=8; cols>=2 zero) ----
    u32 w3f[ED][4];
    #pragma unroll
    for (int e = 0; e < ED; e++) {
        #pragma unroll
        for (int kf = 0; kf < 2; kf++) {
            const int k0 = kf * 16 + 2 * q;
            u32 b0 = 0, b1 = 0;
            if (g < 2) {
                b0 = f16x2_of(gW3[e * 64 + (k0    ) * DO + g], gW3[e * 64 + (k0 + 1) * DO + g]);
                b1 = f16x2_of(gW3[e * 64 + (k0 + 8) * DO + g], gW3[e * 64 + (k0 + 9) * DO + g]);
            }
            w3f[e][kf * 2 + 0] = b0;
            w3f[e][kf * 2 + 1] = b1;
        }
    }
    const u64 b3q0 = *(const u64*)&gb3[(2 * q    ) * DO];
    const u64 b3q1 = *(const u64*)&gb3[(2 * q + 1) * DO];

    const int lim6 = B * DI;
    const float fz = 0.0f;
    const float2 bg2c = ((const float2*)gbg2)[q];

    // ---- persistent per-warp tile loop (32 tokens per warp) ----
    for (int tile = blockIdx.x; tile < NT; tile += gridDim.x) {
        const int base = tile * 128 + w * 32;
        float* sxw = sx + w * 192;
        #pragma unroll
        for (int i = 0; i < 6; i++) {
            const int idx = base * DI + i * 32 + lane;
            sxw[i * 32 + lane] = (idx < lim6) ? gx[idx] : 0.0f;
        }
        __syncwarp();

        // ---- x A-fragments (fp16, k8 layout); q==3 -> 1.0 bias slot ----
        u32 xhi[2][2];
        #pragma unroll
        for (int mf = 0; mf < 2; mf++) {
            const int r0 = 16 * mf + g, r1 = r0 + 8;
            float v00, v01, v10, v11;
            if (q < 3) {
                v00 = sxw[r0 * DI + 2 * q]; v01 = sxw[r0 * DI + 2 * q + 1];
                v10 = sxw[r1 * DI + 2 * q]; v11 = sxw[r1 * DI + 2 * q + 1];
            } else {
                v00 = 1.0f; v01 = 0.0f; v10 = 1.0f; v11 = 0.0f;
            }
            xhi[mf][0] = f16x2_of(v00, v01);
            xhi[mf][1] = f16x2_of(v10, v11);
        }

        // ---- GATE via MMA (f16-D layer-1) + quad-butterfly softmax ----
        float glane[4][2];
        u32 ghp[4];
        {
            const uint4 g1f = *(const uint4*)(sG1frag + lane * 16);
            u32 ag[2][2][4];
            #pragma unroll
            for (int nf = 0; nf < 4; nf++) {
                const u32 bh = (nf == 0) ? g1f.x : (nf == 1) ? g1f.y : (nf == 2) ? g1f.z : g1f.w;
                const int kf = nf >> 1, half = nf & 1;
                #pragma unroll
                for (int mf = 0; mf < 2; mf++) {
                    u32 p0, p1;
                    mma_f16_k8_h16(p0, p1, xhi[mf][0], xhi[mf][1], bh);
                    ag[mf][kf][half * 2 + 0] = hmax2z(p0);
                    ag[mf][kf][half * 2 + 1] = hmax2z(p1);
                }
            }
            const uint4 g2f = *(const uint4*)(sG2frag + lane * 16);
            float gl[2][4];
            #pragma unroll
            for (int mf = 0; mf < 2; mf++) {
                mma_f16_c(gl[mf][0], gl[mf][1], gl[mf][2], gl[mf][3],
                          ag[mf][0][0], ag[mf][0][1], ag[mf][0][2], ag[mf][0][3],
                          g2f.x, g2f.y,
                          bg2c.x, bg2c.y, bg2c.x, bg2c.y);
                mma_f16(gl[mf][0], gl[mf][1], gl[mf][2], gl[mf][3],
                        ag[mf][1][0], ag[mf][1][1], ag[mf][1][2], ag[mf][1][3],
                        g2f.z, g2f.w);
            }
            #pragma unroll
            for (int mf = 0; mf < 2; mf++) {
                #pragma unroll
                for (int r = 0; r < 2; r++) {
                    const int m = 2 * mf + r;
                    const float l0 = gl[mf][r * 2 + 0];
                    const float l1 = gl[mf][r * 2 + 1];
                    float mx = fmaxf(l0, l1);
                    mx = fmaxf(mx, __shfl_xor_sync(0xffffffffu, mx, 1));
                    mx = fmaxf(mx, __shfl_xor_sync(0xffffffffu, mx, 2));
                    const float e0 = __expf(l0 - mx);
                    const float e1 = __expf(l1 - mx);
                    float s = e0 + e1;
                    s += __shfl_xor_sync(0xffffffffu, s, 1);
                    s += __shfl_xor_sync(0xffffffffu, s, 2);
                    const float inv = 1.0f / s;
                    glane[m][0] = e0 * inv;
                    glane[m][1] = e1 * inv;
                    ghp[m] = f16x2_of(glane[m][0], glane[m][1]);
                }
            }
        }

        float acc[2][4];   // persistent layer-3 accumulator (f32)
        u32 gsh[4];

        // ---- experts ----
        #pragma unroll
        for (int e = 0; e < ED; e++) {
            const uint4 b1f = *(const uint4*)(sB1frag + (e * 32 + lane) * 16);
            uint4 cH[4];
            #pragma unroll
            for (int c = 0; c < 4; c++)
                cH[c] = *(const uint4*)(sBfrag + ((e * 4 + c) * 32 + lane) * 16);
            const uint4 b2f = *(const uint4*)&sb2h[(e * 4 + q) * 4];   // f16x2 per nf

            // layer 1: ONE f16-D k8 MMA per (nf,mf) -> packed A-frags
            u32 ahi[2][2][4];
            #pragma unroll
            for (int nf = 0; nf < 4; nf++) {
                const u32 bh = (nf == 0) ? b1f.x : (nf == 1) ? b1f.y : (nf == 2) ? b1f.z : b1f.w;
                const int kf = nf >> 1, half = nf & 1;
                #pragma unroll
                for (int mf = 0; mf < 2; mf++) {
                    u32 p0, p1;
                    mma_f16_k8_h16(p0, p1, xhi[mf][0], xhi[mf][1], bh);
                    ahi[mf][kf][half * 2 + 0] = hmax2z(p0);
                    ahi[mf][kf][half * 2 + 1] = hmax2z(p1);
                }
            }

            // layer-2: TWO f16-D k16 MMAs per (nf,mf), chained; C(first) = packed b2
            u32 dd[2][4][2];
            #pragma unroll
            for (int nf = 0; nf < 4; nf++) {
                const uint4 h40 = cH[0 * 2 + (nf >> 1)];
                const uint4 h41 = cH[1 * 2 + (nf >> 1)];
                const u32 b0k0 = (nf & 1) ? h40.z : h40.x;
                const u32 b1k0 = (nf & 1) ? h40.w : h40.y;
                const u32 b0k1 = (nf & 1) ? h41.z : h41.x;
                const u32 b1k1 = (nf & 1) ? h41.w : h41.y;
                const u32 b2c = (nf == 0) ? b2f.x : (nf == 1) ? b2f.y : (nf == 2) ? b2f.z : b2f.w;
                #pragma unroll
                for (int mf = 0; mf < 2; mf++) {
                    mma_f16_k16_h16_c(dd[mf][nf][0], dd[mf][nf][1],
                                      ahi[mf][0][0], ahi[mf][0][1], ahi[mf][0][2], ahi[mf][0][3],
                                      b0k0, b1k0, b2c, b2c);
                    mma_f16_k16_h16_acc(dd[mf][nf][0], dd[mf][nf][1],
                                        ahi[mf][1][0], ahi[mf][1][1], ahi[mf][1][2], ahi[mf][1][3],
                                        b0k1, b1k1);
                }
            }

            // gate per row: one packed shfl per expert-pair, PRMT dup per expert
            if ((e & 1) == 0) {
                #pragma unroll
                for (int m = 0; m < 4; m++)
                    gsh[m] = __shfl_sync(0xffffffffu, ghp[m], (lane & 28) + (e >> 1));
            }
            const u32 dupsel = (e & 1) ? 0x3232u : 0x1010u;
            u32 geh[4];
            #pragma unroll
            for (int m = 0; m < 4; m++) geh[m] = prmt_sel(gsh[m], dupsel);

            // layer-3 A frags: relu(dd packed) scaled by gate — zero cvts
            u32 a3[2][2][4];
            #pragma unroll
            for (int mf = 0; mf < 2; mf++) {
                #pragma unroll
                for (int nf = 0; nf < 4; nf++) {
                    const int kf = nf >> 1, half = nf & 1;
                    a3[mf][kf][half * 2 + 0] = hmul2(hmax2z(dd[mf][nf][0]), geh[2 * mf + 0]);
                    a3[mf][kf][half * 2 + 1] = hmul2(hmax2z(dd[mf][nf][1]), geh[2 * mf + 1]);
                }
            }

            // layer-3 MMAs (f32 D), accumulating across experts
            #pragma unroll
            for (int mf = 0; mf < 2; mf++) {
                if (e == 0) {
                    mma_f16_c(acc[mf][0], acc[mf][1], acc[mf][2], acc[mf][3],
                              a3[mf][0][0], a3[mf][0][1], a3[mf][0][2], a3[mf][0][3],
                              w3f[e][0], w3f[e][1], fz, fz, fz, fz);
                } else {
                    mma_f16(acc[mf][0], acc[mf][1], acc[mf][2], acc[mf][3],
                            a3[mf][0][0], a3[mf][0][1], a3[mf][0][2], a3[mf][0][3],
                            w3f[e][0], w3f[e][1]);
                }
                mma_f16(acc[mf][0], acc[mf][1], acc[mf][2], acc[mf][3],
                        a3[mf][1][0], a3[mf][1][1], a3[mf][1][2], a3[mf][1][3],
                        w3f[e][2], w3f[e][3]);
            }
        }

        // ---- b3 tail ----
        u64 bias[4];
        #pragma unroll
        for (int m = 0; m < 4; m++) {
            u64 p = mul2(pack_dup(glane[m][0]), b3q0);
            ffma2_acc(p, pack_dup(glane[m][1]), b3q1);
            p = add2(p, __shfl_xor_sync(0xffffffffu, p, 1));
            p = add2(p, __shfl_xor_sync(0xffffffffu, p, 2));
            bias[m] = p;
        }

        // ---- store: q==0 lanes hold cols 0,1 for rows g+8m ----
        if (q == 0) {
            const float2 bb0 = unpack2(bias[0]);
            const float2 bb1 = unpack2(bias[1]);
            const float2 bb2 = unpack2(bias[2]);
            const float2 bb3 = unpack2(bias[3]);
            const int t0 = base + g;
            if (t0 < B)      ((float2*)gout)[t0]      = make_float2(acc[0][0] + bb0.x, acc[0][1] + bb0.y);
            if (t0 + 8 < B)  ((float2*)gout)[t0 + 8]  = make_float2(acc[0][2] + bb1.x, acc[0][3] + bb1.y);
            if (t0 + 16 < B) ((float2*)gout)[t0 + 16] = make_float2(acc[1][0] + bb2.x, acc[1][1] + bb2.y);
            if (t0 + 24 < B) ((float2*)gout)[t0 + 24] = make_float2(acc[1][2] + bb3.x, acc[1][3] + bb3.y);
        }
    }
}

extern "C" void kernel_launch(void* const* d_in, const int* in_sizes, int n_in,
                              void* d_out, int out_size)
{
    const float* x   = (const float*)d_in[0];
    const float* W1  = (const float*)d_in[1];
    const float* b1  = (const float*)d_in[2];
    const float* W2  = (const float*)d_in[3];
    const float* b2  = (const float*)d_in[4];
    const float* W3  = (const float*)d_in[5];
    const float* b3  = (const float*)d_in[6];
    const float* Wg1 = (const float*)d_in[7];
    const float* bg1 = (const float*)d_in[8];
    const float* Wg2 = (const float*)d_in[9];
    const float* bg2 = (const float*)d_in[10];
    float* out = (float*)d_out;

    const int B  = in_sizes[0] / DI;
    const int NT = (B + 127) / 128;

    int nsm = 148;
    cudaDeviceGetAttribute(&nsm, cudaDevAttrMultiProcessorCount, 0);
    int grid = 3 * nsm;          // 3 CTAs/SM
    if (grid > NT) grid = NT;

    moe_mma_kernel<<<grid, 128>>>(x, W1, b1, W2, b2, W3, b3,
                                  Wg1, bg1, Wg2, bg2, out, B, NT);
}